// round 6
// baseline (speedup 1.0000x reference)
#include <cuda_runtime.h>
#include <cuda_fp16.h>
#include <math.h>
#include <stdint.h>

// Problem constants
constexpr int D   = 768;
constexpr int S   = 128;
constexpr int BSN = 4096;    // B*S
constexpr int NN  = 12288;   // 3*B*S
constexpr int H3  = 2304;    // 3*D

// Scratch (device globals — allocation-free rule)
__device__ float  g_x[NN * D];
__device__ float  g_xw[NN * D];
__device__ float  g_gh[(size_t)NN * H3];
__device__ float  g_feats32[S * D];
__device__ __half g_featsh[NN * D];    // feats fp16; reused as y fp16
__device__ __half g_xh[NN * D];        // x fp16; reused as MLP hidden fp16
__device__ __half g_whh_h[H3 * D];
__device__ __half g_wtg_h[D * D];
__device__ __half g_wt1_h[3 * D * D];
__device__ __half g_wt2_h[3 * D * D];
__device__ float  g_sim[S * S];
__device__ float  g_nrm[S];
__device__ float  g_dinv[S];
__device__ float  g_deginv[S];
__device__ float  g_gi[H3];

// ============================ mma.sync helpers =============================
__device__ __forceinline__ uint32_t smem_u32(const void* p) {
    uint32_t a;
    asm("{ .reg .u64 t; cvta.to.shared.u64 t, %1; cvt.u32.u64 %0, t; }"
        : "=r"(a) : "l"(p));
    return a;
}
__device__ __forceinline__ void ldm_x4(uint32_t& r0, uint32_t& r1,
                                       uint32_t& r2, uint32_t& r3, uint32_t addr) {
    asm volatile("ldmatrix.sync.aligned.m8n8.x4.shared.b16 {%0,%1,%2,%3}, [%4];"
                 : "=r"(r0), "=r"(r1), "=r"(r2), "=r"(r3) : "r"(addr));
}
__device__ __forceinline__ void mma_f16(float* c, const uint32_t* a,
                                        const uint32_t* b) {
    asm volatile(
        "mma.sync.aligned.m16n8k16.row.col.f32.f16.f16.f32 "
        "{%0,%1,%2,%3}, {%4,%5,%6,%7}, {%8,%9}, {%0,%1,%2,%3};"
        : "+f"(c[0]), "+f"(c[1]), "+f"(c[2]), "+f"(c[3])
        : "r"(a[0]), "r"(a[1]), "r"(a[2]), "r"(a[3]), "r"(b[0]), "r"(b[1]));
}
#define CP16(dst, src) \
    asm volatile("cp.async.cg.shared.global [%0], [%1], 16;" :: "r"(dst), "l"(src))
#define CP_COMMIT() asm volatile("cp.async.commit_group;" ::: "memory")
#define CP_WAIT2()  asm volatile("cp.async.wait_group 2;" ::: "memory")

// ===========================================================================
// fp16 mma.sync GEMM: C[m,n] = sum_k A[m,k]*B[n,k] (+bias, +relu)
// Block 128x128, BK=32, 8 warps (2m x 4n), warp tile 64x32.
// 4-stage cp.async pipeline, 2 CTAs/SM, 80B-padded SMEM rows.
// B/bias per M-segment (rowSeg) batches the 3 MLP branches.
// ===========================================================================
constexpr int BM = 128, BN = 128, BK = 32;
constexpr int ROWB2 = 80;                         // bytes per SMEM row
constexpr uint32_t A_BYTES = BM * ROWB2;          // 10240
constexpr uint32_t STAGE_BYTES = (BM + BN) * ROWB2;   // 20480
constexpr uint32_t SMEM_BYTES = 4 * STAGE_BYTES;      // 81920

template <int EPI, bool OUTH>  // EPI: 0 none, 1 bias, 2 bias+relu
__global__ void __launch_bounds__(256, 2) h_gemm(
    const __half* __restrict__ A,
    const __half* __restrict__ B0, const __half* __restrict__ B1,
    const __half* __restrict__ B2,
    const float* __restrict__ bias0, const float* __restrict__ bias1,
    const float* __restrict__ bias2,
    void* __restrict__ Cv, int M, int N, int K, int rowSeg)
{
    extern __shared__ char smem[];
    const int bn = blockIdx.x * BN;
    const int bm = blockIdx.y * BM;
    const int seg = bm / rowSeg;
    const __half* Bp  = (seg == 0) ? B0 : ((seg == 1) ? B1 : B2);
    const float* bias = (seg == 0) ? bias0 : ((seg == 1) ? bias1 : bias2);

    const int tid  = threadIdx.x;
    const int lane = tid & 31;
    const int wid  = tid >> 5;
    const int wm   = (wid >> 2) * 64;   // 0 / 64
    const int wn   = (wid & 3) * 32;    // 0/32/64/96

    const uint32_t sS = smem_u32(smem);

    // cp.async loader: 128 A rows + 128 B rows, 64B per row, 4 cp.16/thread
    const int lr = tid >> 1;
    const int ko = (tid & 1) * 16;      // halves
    const __half* Agl = A  + (size_t)(bm + lr) * K + ko;
    const __half* Bgl = Bp + (size_t)(bn + lr) * K + ko;
    const uint32_t aDst = (uint32_t)lr * ROWB2 + ko * 2;
    const uint32_t bDst = A_BYTES + (uint32_t)lr * ROWB2 + ko * 2;

#define LOAD_STAGE(s, kb) do { \
    const int _k0 = (kb) * BK; \
    const uint32_t _base = sS + (uint32_t)(s) * STAGE_BYTES; \
    const __half* _a = Agl + _k0; \
    CP16(_base + aDst, _a); CP16(_base + aDst + 16, _a + 8); \
    const __half* _b = Bgl + _k0; \
    CP16(_base + bDst, _b); CP16(_base + bDst + 16, _b + 8); \
} while (0)

    float c[4][4][4];
#pragma unroll
    for (int i = 0; i < 4; i++)
#pragma unroll
        for (int j = 0; j < 4; j++)
#pragma unroll
            for (int q = 0; q < 4; q++) c[i][j][q] = 0.f;

    LOAD_STAGE(0, 0); CP_COMMIT();
    LOAD_STAGE(1, 1); CP_COMMIT();
    LOAD_STAGE(2, 2); CP_COMMIT();

    // per-lane ldmatrix offsets (bytes)
    const uint32_t aOff = (uint32_t)(wm + (lane & 15)) * ROWB2 + (lane >> 4) * 16;
    const uint32_t bOff = (uint32_t)(wn + (lane & 7) + ((lane >> 4) << 3)) * ROWB2
                          + ((lane >> 3) & 1) * 16;

    const int NS = K / BK;
    for (int ks = 0; ks < NS; ks++) {
        CP_WAIT2();
        __syncthreads();
        if (ks + 3 < NS) {
            LOAD_STAGE((ks + 3) & 3, ks + 3);
            CP_COMMIT();
        } else {
            CP_COMMIT();   // keep group count uniform for wait_group 2
        }
        const uint32_t aB = sS + (uint32_t)(ks & 3) * STAGE_BYTES;
        const uint32_t bB = aB + A_BYTES;
#pragma unroll
        for (int kh = 0; kh < 2; kh++) {
            uint32_t af[4][4], bf[4][2];
#pragma unroll
            for (int mt = 0; mt < 4; mt++)
                ldm_x4(af[mt][0], af[mt][1], af[mt][2], af[mt][3],
                       aB + aOff + kh * 32 + (uint32_t)mt * (16 * ROWB2));
#pragma unroll
            for (int jp = 0; jp < 2; jp++) {
                uint32_t r0, r1, r2, r3;
                ldm_x4(r0, r1, r2, r3,
                       bB + bOff + kh * 32 + (uint32_t)jp * (16 * ROWB2));
                bf[2 * jp][0] = r0;     bf[2 * jp][1] = r1;
                bf[2 * jp + 1][0] = r2; bf[2 * jp + 1][1] = r3;
            }
#pragma unroll
            for (int mt = 0; mt < 4; mt++)
#pragma unroll
                for (int nt = 0; nt < 4; nt++)
                    mma_f16(c[mt][nt], af[mt], bf[nt]);
        }
    }

    // Epilogue
    const int er = lane >> 2;
    const int ec = (lane & 3) * 2;
#pragma unroll
    for (int mt = 0; mt < 4; mt++) {
        const int m = bm + wm + mt * 16 + er;
#pragma unroll
        for (int nt = 0; nt < 4; nt++) {
            const int n = bn + wn + nt * 8 + ec;
            float2 v0 = make_float2(c[mt][nt][0], c[mt][nt][1]);
            float2 v1 = make_float2(c[mt][nt][2], c[mt][nt][3]);
            if (EPI >= 1) {
                float b0 = bias[n], b1 = bias[n + 1];
                v0.x += b0; v0.y += b1;
                v1.x += b0; v1.y += b1;
            }
            if (EPI == 2) {
                v0.x = fmaxf(v0.x, 0.f); v0.y = fmaxf(v0.y, 0.f);
                v1.x = fmaxf(v1.x, 0.f); v1.y = fmaxf(v1.y, 0.f);
            }
            if (OUTH) {
                __half* Ch = (__half*)Cv;
                *(__half2*)(Ch + (size_t)m * N + n)       = __floats2half2_rn(v0.x, v0.y);
                *(__half2*)(Ch + (size_t)(m + 8) * N + n) = __floats2half2_rn(v1.x, v1.y);
            } else {
                float* Cf = (float*)Cv;
                *(float2*)(Cf + (size_t)m * N + n)       = v0;
                *(float2*)(Cf + (size_t)(m + 8) * N + n) = v1;
            }
        }
    }
#undef LOAD_STAGE
}

// ============================ small kernels ================================
__global__ void k_transpose_h(const float* __restrict__ src, __half* __restrict__ dst)
{
    __shared__ float t[32][33];
    int bx = blockIdx.x * 32, by = blockIdx.y * 32;
    int x = bx + threadIdx.x;
#pragma unroll
    for (int j = 0; j < 32; j += 8)
        t[threadIdx.y + j][threadIdx.x] = src[(size_t)(by + threadIdx.y + j) * D + x];
    __syncthreads();
    int ox = by + threadIdx.x;
#pragma unroll
    for (int j = 0; j < 32; j += 8)
        dst[(size_t)(bx + threadIdx.y + j) * D + ox] = __float2half(t[threadIdx.x][threadIdx.y + j]);
}

__global__ void k_cvt_h(const float* __restrict__ src, __half* __restrict__ dst)
{
    int i = blockIdx.x * 256 + threadIdx.x;
    dst[i] = __float2half(src[i]);
}

__global__ void k_gather(const float* __restrict__ a, const float* __restrict__ b,
                         const float* __restrict__ c)
{
    int o = blockIdx.x * 256 + threadIdx.x;
    int n = o / D;
    int d = o - n * D;
    int t = d % 3;
    const float* s = (t == 0) ? a : ((t == 1) ? b : c);
    float v = s[n * (D / 3) + d / 3];
    g_featsh[o] = __float2half(v);
    if (o < S * D) g_feats32[o] = v;
}

__global__ void k_norm()
{
    int i = blockIdx.x;
    float s = 0.f;
    for (int k = threadIdx.x; k < D; k += 256) {
        float v = g_feats32[i * D + k];
        s = fmaf(v, v, s);
    }
    __shared__ float sh[256];
    sh[threadIdx.x] = s; __syncthreads();
    for (int t = 128; t > 0; t >>= 1) {
        if (threadIdx.x < t) sh[threadIdx.x] += sh[threadIdx.x + t];
        __syncthreads();
    }
    if (threadIdx.x == 0) g_nrm[i] = fmaxf(sqrtf(sh[0]), 1e-8f);
}

__global__ void k_sim()
{
    int i = blockIdx.x;
    __shared__ float fi[D];
    for (int k = threadIdx.x; k < D; k += 256) fi[k] = g_feats32[i * D + k];
    __syncthreads();
    int warp = threadIdx.x >> 5, lane = threadIdx.x & 31;
    float ni = g_nrm[i];
    for (int jj = 0; jj < 16; jj++) {
        int j = warp * 16 + jj;
        float s = 0.f;
        for (int k = lane; k < D; k += 32) s = fmaf(fi[k], g_feats32[j * D + k], s);
        for (int o = 16; o > 0; o >>= 1) s += __shfl_down_sync(0xffffffffu, s, o);
        if (lane == 0) g_sim[i * S + j] = s / (ni * g_nrm[j]);
    }
}

__global__ void k_simnorm()
{
    __shared__ float smn[256], smx[256];
    int tid = threadIdx.x;
    float mn = 1e30f, mx = -1e30f;
    for (int e = tid; e < S * S; e += 256) {
        float v = g_sim[e];
        mn = fminf(mn, v); mx = fmaxf(mx, v);
    }
    smn[tid] = mn; smx[tid] = mx;
    __syncthreads();
    for (int t = 128; t > 0; t >>= 1) {
        if (tid < t) {
            smn[tid] = fminf(smn[tid], smn[tid + t]);
            smx[tid] = fmaxf(smx[tid], smx[tid + t]);
        }
        __syncthreads();
    }
    float lo = smn[0];
    float inv = 1.f / (smx[0] - smn[0]);
    __syncthreads();
    for (int e = tid; e < S * S; e += 256) g_sim[e] = (g_sim[e] - lo) * inv;
    __syncthreads();
    if (tid < S) {
        float dg = 1.f;
        for (int i = 0; i < S; i++) dg += g_sim[i * S + tid];
        g_dinv[tid]   = rsqrtf(dg);
        g_deginv[tid] = 1.f / dg;
    }
}

__global__ void k_gcn_first(const float* __restrict__ gcn_b)
{
    int c = blockIdx.x;
    int d = blockIdx.y * 128 + threadIdx.x;
    __shared__ float col[S];
    col[threadIdx.x] = g_dinv[threadIdx.x] * g_sim[threadIdx.x * S + c];
    __syncthreads();
    float acc = 0.f;
#pragma unroll 8
    for (int i = 0; i < S; i++) acc = fmaf(col[i], g_xw[i * D + d], acc);
    float v = g_dinv[c] * acc + g_xw[c * D + d] * g_deginv[c] + gcn_b[d];
    v = fmaxf(v, 0.f);
    g_x[c * D + d] = v;
    g_xh[c * D + d] = __float2half(v);
}

__global__ void k_gcn_rest(const float* __restrict__ gcn_b)
{
    int idx = blockIdx.x * 256 + threadIdx.x;
    int o = S * D + idx;
    int d = o % D;
    float v = fmaxf(g_xw[o] + gcn_b[d], 0.f);
    g_x[o] = v;
    g_xh[o] = __float2half(v);
}

// Fused colsum -> mvec -> gi chain (single block, staged with barriers)
__global__ void __launch_bounds__(1024) k_msg(
    const float* __restrict__ W,
    const float* __restrict__ wih, const float* __restrict__ bih)
{
    __shared__ float sv[D];
    __shared__ float mv[D];
    const int t = threadIdx.x;
    if (t < D) {
        float s = 0.f;
        for (int r = 0; r < S; r++) s += g_x[r * D + t];
        sv[t] = s;
    }
    __syncthreads();
    if (t < D) {
        float a = 0.f;
        for (int k = 0; k < D; k++) a = fmaf(sv[k], W[(size_t)k * D + t], a);
        mv[t] = a;
    }
    __syncthreads();
    const int warp = t >> 5, lane = t & 31;
    for (int o = warp; o < H3; o += 32) {
        float s = 0.f;
        const float* wr = wih + (size_t)o * D;
        for (int k = lane; k < D; k += 32) s = fmaf(mv[k], wr[k], s);
        for (int off = 16; off > 0; off >>= 1) s += __shfl_down_sync(0xffffffffu, s, off);
        if (lane == 0) g_gi[o] = s + bih[o];
    }
}

__global__ void k_gru(const float* __restrict__ bih)
{
    int o = blockIdx.x * 256 + threadIdx.x;
    int n = o / D;
    int d = o - n * D;
    float gir, giz, gin;
    if (n < S) { gir = g_gi[d];  giz = g_gi[D + d];  gin = g_gi[2 * D + d]; }
    else       { gir = bih[d];   giz = bih[D + d];   gin = bih[2 * D + d]; }
    size_t gb = (size_t)n * H3;
    float r  = 1.f / (1.f + expf(-(gir + g_gh[gb + d])));
    float z  = 1.f / (1.f + expf(-(giz + g_gh[gb + D + d])));
    float nn = tanhf(gin + r * g_gh[gb + 2 * D + d]);
    float out = (1.f - z) * nn + z * g_x[o];
    g_x[o] = out;
    g_xh[o] = __float2half(out);
}

__global__ void k_buildy(const float* __restrict__ hfeat)
{
    int o = blockIdx.x * 256 + threadIdx.x;
    g_featsh[o] = __float2half(hfeat[o % (BSN * D)] + fmaxf(g_x[o], 0.f));
}

__global__ void k_ln(const float* __restrict__ g1, const float* __restrict__ be1,
                     const float* __restrict__ g2, const float* __restrict__ be2,
                     const float* __restrict__ g3, const float* __restrict__ be3,
                     float* __restrict__ out)
{
    int r = blockIdx.x;
    int t = r / BSN;
    const float* gg = (t == 0) ? g1 : ((t == 1) ? g2 : g3);
    const float* bb = (t == 0) ? be1 : ((t == 1) ? be2 : be3);
    const float* z = g_gh + (size_t)r * D;
    int tid = threadIdx.x;
    float v0 = z[tid], v1 = z[tid + 256], v2 = z[tid + 512];
    __shared__ float sh[256];
    sh[tid] = v0 + v1 + v2; __syncthreads();
    for (int s = 128; s > 0; s >>= 1) {
        if (tid < s) sh[tid] += sh[tid + s];
        __syncthreads();
    }
    float mu = sh[0] * (1.f / 768.f);
    __syncthreads();
    float d0 = v0 - mu, d1 = v1 - mu, d2 = v2 - mu;
    sh[tid] = d0 * d0 + d1 * d1 + d2 * d2; __syncthreads();
    for (int s = 128; s > 0; s >>= 1) {
        if (tid < s) sh[tid] += sh[tid + s];
        __syncthreads();
    }
    float rstd = rsqrtf(sh[0] * (1.f / 768.f) + 1e-5f);
    float* o = out + (size_t)r * D;
    o[tid]       = d0 * rstd * gg[tid]       + bb[tid];
    o[tid + 256] = d1 * rstd * gg[tid + 256] + bb[tid + 256];
    o[tid + 512] = d2 * rstd * gg[tid + 512] + bb[tid + 512];
}

// ---------------------------------------------------------------------------
extern "C" void kernel_launch(void* const* d_in, const int* in_sizes, int n_in,
                              void* d_out, int out_size)
{
    const float* h_feature = (const float*)d_in[0];
    const float* h_con     = (const float*)d_in[1];
    const float* h_dep     = (const float*)d_in[2];
    const float* h_sem     = (const float*)d_in[3];
    const float* gcn_W     = (const float*)d_in[4];
    const float* gcn_b     = (const float*)d_in[5];
    const float* ggc_W     = (const float*)d_in[6];
    const float* gru_wih   = (const float*)d_in[7];
    const float* gru_whh   = (const float*)d_in[8];
    const float* gru_bih   = (const float*)d_in[9];
    const float* gru_bhh   = (const float*)d_in[10];
    const float* rW1[3]   = {(const float*)d_in[11], (const float*)d_in[17], (const float*)d_in[23]};
    const float* rb1[3]   = {(const float*)d_in[12], (const float*)d_in[18], (const float*)d_in[24]};
    const float* rW2[3]   = {(const float*)d_in[13], (const float*)d_in[19], (const float*)d_in[25]};
    const float* rb2[3]   = {(const float*)d_in[14], (const float*)d_in[20], (const float*)d_in[26]};
    const float* rg[3]    = {(const float*)d_in[15], (const float*)d_in[21], (const float*)d_in[27]};
    const float* rbeta[3] = {(const float*)d_in[16], (const float*)d_in[22], (const float*)d_in[28]};
    float* out = (float*)d_out;

    float *x, *xw, *gh;
    __half *featsh, *xh, *whh_h, *wtg_h, *wt1_h, *wt2_h;
    cudaGetSymbolAddress((void**)&x,      g_x);
    cudaGetSymbolAddress((void**)&xw,     g_xw);
    cudaGetSymbolAddress((void**)&gh,     g_gh);
    cudaGetSymbolAddress((void**)&featsh, g_featsh);
    cudaGetSymbolAddress((void**)&xh,     g_xh);
    cudaGetSymbolAddress((void**)&whh_h,  g_whh_h);
    cudaGetSymbolAddress((void**)&wtg_h,  g_wtg_h);
    cudaGetSymbolAddress((void**)&wt1_h,  g_wt1_h);
    cudaGetSymbolAddress((void**)&wt2_h,  g_wt2_h);

    cudaFuncSetAttribute(h_gemm<0, false>, cudaFuncAttributeMaxDynamicSharedMemorySize, SMEM_BYTES);
    cudaFuncSetAttribute(h_gemm<1, false>, cudaFuncAttributeMaxDynamicSharedMemorySize, SMEM_BYTES);
    cudaFuncSetAttribute(h_gemm<2, true>,  cudaFuncAttributeMaxDynamicSharedMemorySize, SMEM_BYTES);

    dim3 tb(32, 8);
    dim3 tg(D / 32, D / 32);

    // 1) feats gather + graph scalars + fp16 weight prep
    k_gather<<<NN * D / 256, 256>>>(h_con, h_dep, h_sem);
    k_norm<<<S, 256>>>();
    k_sim<<<S, 256>>>();
    k_simnorm<<<1, 256>>>();
    k_transpose_h<<<tg, tb>>>(gcn_W, wtg_h);
    for (int t = 0; t < 3; t++) {
        k_transpose_h<<<tg, tb>>>(rW1[t], wt1_h + (size_t)t * D * D);
        k_transpose_h<<<tg, tb>>>(rW2[t], wt2_h + (size_t)t * D * D);
    }
    k_cvt_h<<<H3 * D / 256, 256>>>(gru_whh, whh_h);

    // 2) xw = feats @ gcn_W (B = gcn_W^T fp16)
    h_gemm<0, false><<<dim3(D / BN, NN / BM), 256, SMEM_BYTES>>>(
        featsh, wtg_h, wtg_h, wtg_h, nullptr, nullptr, nullptr,
        xw, NN, D, D, NN);

    // 3) GCN aggregation + relu -> g_x (+fp16 copy)
    {
        dim3 g(S, D / 128);
        k_gcn_first<<<g, 128>>>(gcn_b);
    }
    k_gcn_rest<<<(NN - S) * D / 256, 256>>>(gcn_b);

    // 4) GatedGraphConv: 2 layers
    for (int l = 0; l < 2; l++) {
        k_msg<<<1, 1024>>>(ggc_W + (size_t)l * D * D, gru_wih, gru_bih);
        h_gemm<1, false><<<dim3(H3 / BN, NN / BM), 256, SMEM_BYTES>>>(
            xh, whh_h, whh_h, whh_h, gru_bhh, gru_bhh, gru_bhh,
            gh, NN, H3, D, NN);
        k_gru<<<NN * D / 256, 256>>>(gru_bih);
    }

    // 5) y = h_feature + relu(x) -> fp16 (into g_featsh)
    k_buildy<<<NN * D / 256, 256>>>(h_feature);

    // 6) three residual MLPs, batched over M=12288 with per-segment weights
    h_gemm<2, true><<<dim3(D / BN, NN / BM), 256, SMEM_BYTES>>>(
        featsh, wt1_h, wt1_h + (size_t)D * D, wt1_h + 2 * (size_t)D * D,
        rb1[0], rb1[1], rb1[2], xh, NN, D, D, BSN);
    h_gemm<1, false><<<dim3(D / BN, NN / BM), 256, SMEM_BYTES>>>(
        xh, wt2_h, wt2_h + (size_t)D * D, wt2_h + 2 * (size_t)D * D,
        rb2[0], rb2[1], rb2[2], gh, NN, D, D, BSN);

    // 7) LayerNorm -> d_out
    k_ln<<<NN, 256>>>(rg[0], rbeta[0], rg[1], rbeta[1], rg[2], rbeta[2], out);
}

// round 7
// speedup vs baseline: 1.0730x; 1.0730x over previous
#include <cuda_runtime.h>
#include <cuda_fp16.h>
#include <math.h>
#include <stdint.h>

// Problem constants
constexpr int D   = 768;
constexpr int S   = 128;
constexpr int BSN = 4096;    // B*S
constexpr int NN  = 12288;   // 3*B*S
constexpr int H3  = 2304;    // 3*D

// Scratch (device globals — allocation-free rule)
__device__ float  g_x[NN * D];
__device__ float  g_xw[NN * D];
__device__ float  g_z[NN * D];         // MLP pre-LN output
__device__ float  g_feats32[S * D];
__device__ __half g_featsh[NN * D];    // feats fp16; reused as y fp16
__device__ __half g_xh[NN * D];        // x fp16 ping; reused as MLP hidden
__device__ __half g_xh2[NN * D];       // x fp16 pong
__device__ __half g_whh_h[H3 * D];
__device__ __half g_wtg_h[D * D];
__device__ __half g_wt1_h[3 * D * D];
__device__ __half g_wt2_h[3 * D * D];
__device__ float  g_sim[S * S];
__device__ float  g_nrm[S];
__device__ float  g_dinv[S];
__device__ float  g_deginv[S];
__device__ float  g_gi[H3];

// ============================ mma.sync helpers =============================
__device__ __forceinline__ uint32_t smem_u32(const void* p) {
    uint32_t a;
    asm("{ .reg .u64 t; cvta.to.shared.u64 t, %1; cvt.u32.u64 %0, t; }"
        : "=r"(a) : "l"(p));
    return a;
}
__device__ __forceinline__ void ldm_x4(uint32_t& r0, uint32_t& r1,
                                       uint32_t& r2, uint32_t& r3, uint32_t addr) {
    asm volatile("ldmatrix.sync.aligned.m8n8.x4.shared.b16 {%0,%1,%2,%3}, [%4];"
                 : "=r"(r0), "=r"(r1), "=r"(r2), "=r"(r3) : "r"(addr));
}
__device__ __forceinline__ void mma_f16(float* c, const uint32_t* a,
                                        const uint32_t* b) {
    asm volatile(
        "mma.sync.aligned.m16n8k16.row.col.f32.f16.f16.f32 "
        "{%0,%1,%2,%3}, {%4,%5,%6,%7}, {%8,%9}, {%0,%1,%2,%3};"
        : "+f"(c[0]), "+f"(c[1]), "+f"(c[2]), "+f"(c[3])
        : "r"(a[0]), "r"(a[1]), "r"(a[2]), "r"(a[3]), "r"(b[0]), "r"(b[1]));
}
__device__ __forceinline__ float sigm(float v) { return 1.f / (1.f + expf(-v)); }
#define CP16(dst, src) \
    asm volatile("cp.async.cg.shared.global [%0], [%1], 16;" :: "r"(dst), "l"(src))
#define CP_COMMIT() asm volatile("cp.async.commit_group;" ::: "memory")
#define CP_WAIT1()  asm volatile("cp.async.wait_group 1;" ::: "memory")

// ===========================================================================
// fp16 mma.sync GEMM (R5-proven): C[m,n] = sum_k A[m,k]*B[n,k] (+bias,+relu)
// Block 128x256, BK=32, 8 warps (2m x 4n), warp tile 64x64, 3-stage cp.async.
// ===========================================================================
constexpr int BM = 128, BN = 256, BK = 32;
constexpr int ROWB2 = 80;
constexpr uint32_t A_BYTES = BM * ROWB2;              // 10240
constexpr uint32_t STAGE_BYTES = (BM + BN) * ROWB2;   // 30720
constexpr uint32_t SMEM_BYTES = 3 * STAGE_BYTES;      // 92160

template <int EPI, bool OUTH>  // EPI: 0 none, 1 bias, 2 bias+relu
__global__ void __launch_bounds__(256, 1) h_gemm(
    const __half* __restrict__ A,
    const __half* __restrict__ B0, const __half* __restrict__ B1,
    const __half* __restrict__ B2,
    const float* __restrict__ bias0, const float* __restrict__ bias1,
    const float* __restrict__ bias2,
    void* __restrict__ Cv, int M, int N, int K, int rowSeg)
{
    extern __shared__ char smem[];
    const int bn = blockIdx.x * BN;
    const int bm = blockIdx.y * BM;
    const int seg = bm / rowSeg;
    const __half* Bp  = (seg == 0) ? B0 : ((seg == 1) ? B1 : B2);
    const float* bias = (seg == 0) ? bias0 : ((seg == 1) ? bias1 : bias2);

    const int tid  = threadIdx.x;
    const int lane = tid & 31;
    const int wid  = tid >> 5;
    const int wm   = (wid >> 2) * 64;
    const int wn   = (wid & 3) * 64;

    const uint32_t sS = smem_u32(smem);

    const int lr = tid >> 1;
    const int ko = (tid & 1) * 16;
    const __half* Agl = A  + (size_t)(bm + lr) * K + ko;
    const __half* Bgl = Bp + (size_t)(bn + lr) * K + ko;
    const uint32_t aDst = (uint32_t)lr * ROWB2 + ko * 2;
    const uint32_t bDst = A_BYTES + (uint32_t)lr * ROWB2 + ko * 2;

#define LOAD_STAGE(s, kb) do { \
    const int _k0 = (kb) * BK; \
    const uint32_t _base = sS + (uint32_t)(s) * STAGE_BYTES; \
    const __half* _a = Agl + _k0; \
    CP16(_base + aDst, _a); CP16(_base + aDst + 16, _a + 8); \
    const __half* _b = Bgl + _k0; \
    CP16(_base + bDst, _b); CP16(_base + bDst + 16, _b + 8); \
    _b += (size_t)128 * K; \
    CP16(_base + bDst + 128 * ROWB2, _b); \
    CP16(_base + bDst + 128 * ROWB2 + 16, _b + 8); \
} while (0)

    float c[4][8][4];
#pragma unroll
    for (int i = 0; i < 4; i++)
#pragma unroll
        for (int j = 0; j < 8; j++)
#pragma unroll
            for (int q = 0; q < 4; q++) c[i][j][q] = 0.f;

    LOAD_STAGE(0, 0); CP_COMMIT();
    LOAD_STAGE(1, 1); CP_COMMIT();

    const uint32_t aOff = (uint32_t)(wm + (lane & 15)) * ROWB2 + (lane >> 4) * 16;
    const uint32_t bOff = (uint32_t)(wn + (lane & 7) + ((lane >> 4) << 3)) * ROWB2
                          + ((lane >> 3) & 1) * 16;

    const int NS = K / BK;
    for (int ks = 0; ks < NS; ks++) {
        CP_WAIT1();
        __syncthreads();
        if (ks + 2 < NS) {
            LOAD_STAGE((ks + 2) % 3, ks + 2);
            CP_COMMIT();
        }
        const uint32_t aB = sS + (uint32_t)(ks % 3) * STAGE_BYTES;
        const uint32_t bB = aB + A_BYTES;
#pragma unroll
        for (int kh = 0; kh < 2; kh++) {
            uint32_t af[4][4], bf[8][2];
#pragma unroll
            for (int mt = 0; mt < 4; mt++)
                ldm_x4(af[mt][0], af[mt][1], af[mt][2], af[mt][3],
                       aB + aOff + kh * 32 + (uint32_t)mt * (16 * ROWB2));
#pragma unroll
            for (int jp = 0; jp < 4; jp++) {
                uint32_t r0, r1, r2, r3;
                ldm_x4(r0, r1, r2, r3,
                       bB + bOff + kh * 32 + (uint32_t)jp * (16 * ROWB2));
                bf[2 * jp][0] = r0;     bf[2 * jp][1] = r1;
                bf[2 * jp + 1][0] = r2; bf[2 * jp + 1][1] = r3;
            }
#pragma unroll
            for (int mt = 0; mt < 4; mt++)
#pragma unroll
                for (int nt = 0; nt < 8; nt++)
                    mma_f16(c[mt][nt], af[mt], bf[nt]);
        }
    }

    const int er = lane >> 2;
    const int ec = (lane & 3) * 2;
#pragma unroll
    for (int mt = 0; mt < 4; mt++) {
        const int m = bm + wm + mt * 16 + er;
#pragma unroll
        for (int nt = 0; nt < 8; nt++) {
            const int n = bn + wn + nt * 8 + ec;
            float2 v0 = make_float2(c[mt][nt][0], c[mt][nt][1]);
            float2 v1 = make_float2(c[mt][nt][2], c[mt][nt][3]);
            if (EPI >= 1) {
                float b0 = bias[n], b1 = bias[n + 1];
                v0.x += b0; v0.y += b1;
                v1.x += b0; v1.y += b1;
            }
            if (EPI == 2) {
                v0.x = fmaxf(v0.x, 0.f); v0.y = fmaxf(v0.y, 0.f);
                v1.x = fmaxf(v1.x, 0.f); v1.y = fmaxf(v1.y, 0.f);
            }
            if (OUTH) {
                __half* Ch = (__half*)Cv;
                *(__half2*)(Ch + (size_t)m * N + n)       = __floats2half2_rn(v0.x, v0.y);
                *(__half2*)(Ch + (size_t)(m + 8) * N + n) = __floats2half2_rn(v1.x, v1.y);
            } else {
                float* Cf = (float*)Cv;
                *(float2*)(Cf + (size_t)m * N + n)       = v0;
                *(float2*)(Cf + (size_t)(m + 8) * N + n) = v1;
            }
        }
    }
#undef LOAD_STAGE
}

// ===========================================================================
// Fused GRU-GEMM: computes gh_r/gh_z/gh_n for a (128 x 64) (m,d) tile via
// 3 accumulator sets over K=768, then applies the full GRU update in the
// epilogue. Eliminates the g_gh intermediate and the k_gru kernel.
// A = fp16 state (read-only), out: g_x (fp32, in/out) + Xh (fp16, new buffer).
// ===========================================================================
constexpr uint32_t GA_BYTES = 128 * 80;              // 10240
constexpr uint32_t GSTAGE   = GA_BYTES + 192 * 80;   // 25600
constexpr uint32_t GSMEM    = 3 * GSTAGE;            // 76800

__global__ void __launch_bounds__(256, 1) h_gru(
    const __half* __restrict__ A, const __half* __restrict__ Whh,
    const float* __restrict__ bhh, const float* __restrict__ bih,
    float* __restrict__ X, __half* __restrict__ Xh)
{
    extern __shared__ char smem[];
    const int bd = blockIdx.x * 64;
    const int bm = blockIdx.y * 128;
    const int tid = threadIdx.x, lane = tid & 31, wid = tid >> 5;
    const int wm = (wid >> 2) * 64;
    const int wn = (wid & 3) * 16;
    const uint32_t sS = smem_u32(smem);

    // loader: 128 A rows + 3x64 B rows, 64B/row, 4x16B pieces; 5 cp per thread
    const int piece = tid & 3;
    const int rbase = tid >> 2;   // 0..63
    const __half* aS0 = A   + (size_t)(bm + rbase) * D      + piece * 8;
    const __half* aS1 = A   + (size_t)(bm + rbase + 64) * D + piece * 8;
    const __half* bS0 = Whh + (size_t)(bd + rbase) * D              + piece * 8;
    const __half* bS1 = Whh + (size_t)(768 + bd + rbase) * D        + piece * 8;
    const __half* bS2 = Whh + (size_t)(1536 + bd + rbase) * D       + piece * 8;
    const uint32_t dA0 = (uint32_t)rbase * 80 + piece * 16;
    const uint32_t dA1 = dA0 + 64 * 80;
    const uint32_t dB0 = GA_BYTES + (uint32_t)rbase * 80 + piece * 16;
    const uint32_t dB1 = dB0 + 64 * 80;
    const uint32_t dB2 = dB0 + 128 * 80;

#define GLOAD(s, kb) do { \
    const int _k0 = (kb) * 32; \
    const uint32_t _b = sS + (uint32_t)(s) * GSTAGE; \
    CP16(_b + dA0, aS0 + _k0); \
    CP16(_b + dA1, aS1 + _k0); \
    CP16(_b + dB0, bS0 + _k0); \
    CP16(_b + dB1, bS1 + _k0); \
    CP16(_b + dB2, bS2 + _k0); \
} while (0)

    float c[3][4][2][4];
#pragma unroll
    for (int g = 0; g < 3; g++)
#pragma unroll
        for (int i = 0; i < 4; i++)
#pragma unroll
            for (int j = 0; j < 2; j++)
#pragma unroll
                for (int q = 0; q < 4; q++) c[g][i][j][q] = 0.f;

    GLOAD(0, 0); CP_COMMIT();
    GLOAD(1, 1); CP_COMMIT();

    const uint32_t aOff = (uint32_t)(wm + (lane & 15)) * 80 + (lane >> 4) * 16;
    const uint32_t bOff = (uint32_t)(wn + (lane & 7) + ((lane >> 4) << 3)) * 80
                          + ((lane >> 3) & 1) * 16;

    const int NS = D / 32;   // 24
    for (int ks = 0; ks < NS; ks++) {
        CP_WAIT1();
        __syncthreads();
        if (ks + 2 < NS) {
            GLOAD((ks + 2) % 3, ks + 2);
            CP_COMMIT();
        }
        const uint32_t aB = sS + (uint32_t)(ks % 3) * GSTAGE;
        const uint32_t bB = aB + GA_BYTES;
#pragma unroll
        for (int kh = 0; kh < 2; kh++) {
            uint32_t af[4][4], bf[3][4];
#pragma unroll
            for (int mt = 0; mt < 4; mt++)
                ldm_x4(af[mt][0], af[mt][1], af[mt][2], af[mt][3],
                       aB + aOff + kh * 32 + (uint32_t)mt * (16 * 80));
#pragma unroll
            for (int g = 0; g < 3; g++)
                ldm_x4(bf[g][0], bf[g][1], bf[g][2], bf[g][3],
                       bB + (uint32_t)g * (64 * 80) + bOff + kh * 32);
#pragma unroll
            for (int g = 0; g < 3; g++)
#pragma unroll
                for (int mt = 0; mt < 4; mt++) {
                    mma_f16(c[g][mt][0], af[mt], &bf[g][0]);
                    mma_f16(c[g][mt][1], af[mt], &bf[g][2]);
                }
        }
    }

    // GRU epilogue
    const int er = lane >> 2;
    const int ec = (lane & 3) * 2;
    const bool first = (bm == 0);   // whole tile is nodes < S
#pragma unroll
    for (int nt = 0; nt < 2; nt++) {
        const int d0 = bd + wn + nt * 8 + ec;
        const float br0 = bhh[d0],        br1 = bhh[d0 + 1];
        const float bz0 = bhh[768 + d0],  bz1 = bhh[768 + d0 + 1];
        const float bn0 = bhh[1536 + d0], bn1 = bhh[1536 + d0 + 1];
        const float gr0 = first ? g_gi[d0]        : bih[d0];
        const float gr1 = first ? g_gi[d0 + 1]    : bih[d0 + 1];
        const float gz0 = first ? g_gi[768 + d0]  : bih[768 + d0];
        const float gz1 = first ? g_gi[768 + d0 + 1] : bih[768 + d0 + 1];
        const float gn0 = first ? g_gi[1536 + d0] : bih[1536 + d0];
        const float gn1 = first ? g_gi[1536 + d0 + 1] : bih[1536 + d0 + 1];
#pragma unroll
        for (int mt = 0; mt < 4; mt++) {
#pragma unroll
            for (int hf = 0; hf < 2; hf++) {
                const int row = bm + wm + mt * 16 + er + 8 * hf;
                float2 h2 = *(float2*)(X + (size_t)row * D + d0);
                const int q = hf * 2;
                float r0 = sigm(gr0 + c[0][mt][nt][q]     + br0);
                float r1 = sigm(gr1 + c[0][mt][nt][q + 1] + br1);
                float z0 = sigm(gz0 + c[1][mt][nt][q]     + bz0);
                float z1 = sigm(gz1 + c[1][mt][nt][q + 1] + bz1);
                float n0 = tanhf(gn0 + r0 * (c[2][mt][nt][q]     + bn0));
                float n1 = tanhf(gn1 + r1 * (c[2][mt][nt][q + 1] + bn1));
                float o0 = (1.f - z0) * n0 + z0 * h2.x;
                float o1 = (1.f - z1) * n1 + z1 * h2.y;
                *(float2*)(X + (size_t)row * D + d0) = make_float2(o0, o1);
                *(__half2*)(Xh + (size_t)row * D + d0) = __floats2half2_rn(o0, o1);
            }
        }
    }
#undef GLOAD
}

// ============================ small kernels ================================
__global__ void k_transpose_h(const float* __restrict__ src, __half* __restrict__ dst)
{
    __shared__ float t[32][33];
    int bx = blockIdx.x * 32, by = blockIdx.y * 32;
    int x = bx + threadIdx.x;
#pragma unroll
    for (int j = 0; j < 32; j += 8)
        t[threadIdx.y + j][threadIdx.x] = src[(size_t)(by + threadIdx.y + j) * D + x];
    __syncthreads();
    int ox = by + threadIdx.x;
#pragma unroll
    for (int j = 0; j < 32; j += 8)
        dst[(size_t)(bx + threadIdx.y + j) * D + ox] = __float2half(t[threadIdx.x][threadIdx.y + j]);
}

__global__ void k_cvt_h(const float* __restrict__ src, __half* __restrict__ dst)
{
    int i = blockIdx.x * 256 + threadIdx.x;
    dst[i] = __float2half(src[i]);
}

__global__ void k_gather(const float* __restrict__ a, const float* __restrict__ b,
                         const float* __restrict__ c)
{
    int o = blockIdx.x * 256 + threadIdx.x;
    int n = o / D;
    int d = o - n * D;
    int t = d % 3;
    const float* s = (t == 0) ? a : ((t == 1) ? b : c);
    float v = s[n * (D / 3) + d / 3];
    g_featsh[o] = __float2half(v);
    if (o < S * D) g_feats32[o] = v;
}

__global__ void k_norm()
{
    int i = blockIdx.x;
    float s = 0.f;
    for (int k = threadIdx.x; k < D; k += 256) {
        float v = g_feats32[i * D + k];
        s = fmaf(v, v, s);
    }
    __shared__ float sh[256];
    sh[threadIdx.x] = s; __syncthreads();
    for (int t = 128; t > 0; t >>= 1) {
        if (threadIdx.x < t) sh[threadIdx.x] += sh[threadIdx.x + t];
        __syncthreads();
    }
    if (threadIdx.x == 0) g_nrm[i] = fmaxf(sqrtf(sh[0]), 1e-8f);
}

__global__ void k_sim()
{
    int i = blockIdx.x;
    __shared__ float fi[D];
    for (int k = threadIdx.x; k < D; k += 256) fi[k] = g_feats32[i * D + k];
    __syncthreads();
    int warp = threadIdx.x >> 5, lane = threadIdx.x & 31;
    float ni = g_nrm[i];
    for (int jj = 0; jj < 16; jj++) {
        int j = warp * 16 + jj;
        float s = 0.f;
        for (int k = lane; k < D; k += 32) s = fmaf(fi[k], g_feats32[j * D + k], s);
        for (int o = 16; o > 0; o >>= 1) s += __shfl_down_sync(0xffffffffu, s, o);
        if (lane == 0) g_sim[i * S + j] = s / (ni * g_nrm[j]);
    }
}

__global__ void k_simnorm()
{
    __shared__ float smn[256], smx[256];
    int tid = threadIdx.x;
    float mn = 1e30f, mx = -1e30f;
    for (int e = tid; e < S * S; e += 256) {
        float v = g_sim[e];
        mn = fminf(mn, v); mx = fmaxf(mx, v);
    }
    smn[tid] = mn; smx[tid] = mx;
    __syncthreads();
    for (int t = 128; t > 0; t >>= 1) {
        if (tid < t) {
            smn[tid] = fminf(smn[tid], smn[tid + t]);
            smx[tid] = fmaxf(smx[tid], smx[tid + t]);
        }
        __syncthreads();
    }
    float lo = smn[0];
    float inv = 1.f / (smx[0] - smn[0]);
    __syncthreads();
    for (int e = tid; e < S * S; e += 256) g_sim[e] = (g_sim[e] - lo) * inv;
    __syncthreads();
    if (tid < S) {
        float dg = 1.f;
        for (int i = 0; i < S; i++) dg += g_sim[i * S + tid];
        g_dinv[tid]   = rsqrtf(dg);
        g_deginv[tid] = 1.f / dg;
    }
}

__global__ void k_gcn_first(const float* __restrict__ gcn_b)
{
    int c = blockIdx.x;
    int d = blockIdx.y * 128 + threadIdx.x;
    __shared__ float col[S];
    col[threadIdx.x] = g_dinv[threadIdx.x] * g_sim[threadIdx.x * S + c];
    __syncthreads();
    float acc = 0.f;
#pragma unroll 8
    for (int i = 0; i < S; i++) acc = fmaf(col[i], g_xw[i * D + d], acc);
    float v = g_dinv[c] * acc + g_xw[c * D + d] * g_deginv[c] + gcn_b[d];
    v = fmaxf(v, 0.f);
    g_x[c * D + d] = v;
    g_xh[c * D + d] = __float2half(v);
}

__global__ void k_gcn_rest(const float* __restrict__ gcn_b)
{
    int idx = blockIdx.x * 256 + threadIdx.x;
    int o = S * D + idx;
    int d = o % D;
    float v = fmaxf(g_xw[o] + gcn_b[d], 0.f);
    g_x[o] = v;
    g_xh[o] = __float2half(v);
}

// Fused colsum -> mvec -> gi chain (single block)
__global__ void __launch_bounds__(1024) k_msg(
    const float* __restrict__ W,
    const float* __restrict__ wih, const float* __restrict__ bih)
{
    __shared__ float sv[D];
    __shared__ float mv[D];
    const int t = threadIdx.x;
    if (t < D) {
        float s = 0.f;
        for (int r = 0; r < S; r++) s += g_x[r * D + t];
        sv[t] = s;
    }
    __syncthreads();
    if (t < D) {
        float a = 0.f;
        for (int k = 0; k < D; k++) a = fmaf(sv[k], W[(size_t)k * D + t], a);
        mv[t] = a;
    }
    __syncthreads();
    const int warp = t >> 5, lane = t & 31;
    for (int o = warp; o < H3; o += 32) {
        float s = 0.f;
        const float* wr = wih + (size_t)o * D;
        for (int k = lane; k < D; k += 32) s = fmaf(mv[k], wr[k], s);
        for (int off = 16; off > 0; off >>= 1) s += __shfl_down_sync(0xffffffffu, s, off);
        if (lane == 0) g_gi[o] = s + bih[o];
    }
}

__global__ void k_buildy(const float* __restrict__ hfeat)
{
    int o = blockIdx.x * 256 + threadIdx.x;
    g_featsh[o] = __float2half(hfeat[o % (BSN * D)] + fmaxf(g_x[o], 0.f));
}

__global__ void k_ln(const float* __restrict__ g1, const float* __restrict__ be1,
                     const float* __restrict__ g2, const float* __restrict__ be2,
                     const float* __restrict__ g3, const float* __restrict__ be3,
                     float* __restrict__ out)
{
    int r = blockIdx.x;
    int t = r / BSN;
    const float* gg = (t == 0) ? g1 : ((t == 1) ? g2 : g3);
    const float* bb = (t == 0) ? be1 : ((t == 1) ? be2 : be3);
    const float* z = g_z + (size_t)r * D;
    int tid = threadIdx.x;
    float v0 = z[tid], v1 = z[tid + 256], v2 = z[tid + 512];
    __shared__ float sh[256];
    sh[tid] = v0 + v1 + v2; __syncthreads();
    for (int s = 128; s > 0; s >>= 1) {
        if (tid < s) sh[tid] += sh[tid + s];
        __syncthreads();
    }
    float mu = sh[0] * (1.f / 768.f);
    __syncthreads();
    float d0 = v0 - mu, d1 = v1 - mu, d2 = v2 - mu;
    sh[tid] = d0 * d0 + d1 * d1 + d2 * d2; __syncthreads();
    for (int s = 128; s > 0; s >>= 1) {
        if (tid < s) sh[tid] += sh[tid + s];
        __syncthreads();
    }
    float rstd = rsqrtf(sh[0] * (1.f / 768.f) + 1e-5f);
    float* o = out + (size_t)r * D;
    o[tid]       = d0 * rstd * gg[tid]       + bb[tid];
    o[tid + 256] = d1 * rstd * gg[tid + 256] + bb[tid + 256];
    o[tid + 512] = d2 * rstd * gg[tid + 512] + bb[tid + 512];
}

// ---------------------------------------------------------------------------
extern "C" void kernel_launch(void* const* d_in, const int* in_sizes, int n_in,
                              void* d_out, int out_size)
{
    const float* h_feature = (const float*)d_in[0];
    const float* h_con     = (const float*)d_in[1];
    const float* h_dep     = (const float*)d_in[2];
    const float* h_sem     = (const float*)d_in[3];
    const float* gcn_W     = (const float*)d_in[4];
    const float* gcn_b     = (const float*)d_in[5];
    const float* ggc_W     = (const float*)d_in[6];
    const float* gru_wih   = (const float*)d_in[7];
    const float* gru_whh   = (const float*)d_in[8];
    const float* gru_bih   = (const float*)d_in[9];
    const float* gru_bhh   = (const float*)d_in[10];
    const float* rW1[3]   = {(const float*)d_in[11], (const float*)d_in[17], (const float*)d_in[23]};
    const float* rb1[3]   = {(const float*)d_in[12], (const float*)d_in[18], (const float*)d_in[24]};
    const float* rW2[3]   = {(const float*)d_in[13], (const float*)d_in[19], (const float*)d_in[25]};
    const float* rb2[3]   = {(const float*)d_in[14], (const float*)d_in[20], (const float*)d_in[26]};
    const float* rg[3]    = {(const float*)d_in[15], (const float*)d_in[21], (const float*)d_in[27]};
    const float* rbeta[3] = {(const float*)d_in[16], (const float*)d_in[22], (const float*)d_in[28]};
    float* out = (float*)d_out;

    float *x, *xw, *zbuf;
    __half *featsh, *xh, *xh2, *whh_h, *wtg_h, *wt1_h, *wt2_h;
    cudaGetSymbolAddress((void**)&x,      g_x);
    cudaGetSymbolAddress((void**)&xw,     g_xw);
    cudaGetSymbolAddress((void**)&zbuf,   g_z);
    cudaGetSymbolAddress((void**)&featsh, g_featsh);
    cudaGetSymbolAddress((void**)&xh,     g_xh);
    cudaGetSymbolAddress((void**)&xh2,    g_xh2);
    cudaGetSymbolAddress((void**)&whh_h,  g_whh_h);
    cudaGetSymbolAddress((void**)&wtg_h,  g_wtg_h);
    cudaGetSymbolAddress((void**)&wt1_h,  g_wt1_h);
    cudaGetSymbolAddress((void**)&wt2_h,  g_wt2_h);

    cudaFuncSetAttribute(h_gemm<0, false>, cudaFuncAttributeMaxDynamicSharedMemorySize, SMEM_BYTES);
    cudaFuncSetAttribute(h_gemm<1, false>, cudaFuncAttributeMaxDynamicSharedMemorySize, SMEM_BYTES);
    cudaFuncSetAttribute(h_gemm<2, true>,  cudaFuncAttributeMaxDynamicSharedMemorySize, SMEM_BYTES);
    cudaFuncSetAttribute(h_gru, cudaFuncAttributeMaxDynamicSharedMemorySize, GSMEM);

    dim3 tb(32, 8);
    dim3 tg(D / 32, D / 32);

    // 1) feats gather + graph scalars + fp16 weight prep
    k_gather<<<NN * D / 256, 256>>>(h_con, h_dep, h_sem);
    k_norm<<<S, 256>>>();
    k_sim<<<S, 256>>>();
    k_simnorm<<<1, 256>>>();
    k_transpose_h<<<tg, tb>>>(gcn_W, wtg_h);
    for (int t = 0; t < 3; t++) {
        k_transpose_h<<<tg, tb>>>(rW1[t], wt1_h + (size_t)t * D * D);
        k_transpose_h<<<tg, tb>>>(rW2[t], wt2_h + (size_t)t * D * D);
    }
    k_cvt_h<<<H3 * D / 256, 256>>>(gru_whh, whh_h);

    // 2) xw = feats @ gcn_W
    h_gemm<0, false><<<dim3(D / BN, NN / BM), 256, SMEM_BYTES>>>(
        featsh, wtg_h, wtg_h, wtg_h, nullptr, nullptr, nullptr,
        xw, NN, D, D, NN);

    // 3) GCN aggregation + relu -> g_x (+fp16 copy)
    {
        dim3 g(S, D / 128);
        k_gcn_first<<<g, 128>>>(gcn_b);
    }
    k_gcn_rest<<<(NN - S) * D / 256, 256>>>(gcn_b);

    // 4) GatedGraphConv: 2 layers, fully fused GRU
    for (int l = 0; l < 2; l++) {
        k_msg<<<1, 1024>>>(ggc_W + (size_t)l * D * D, gru_wih, gru_bih);
        h_gru<<<dim3(D / 64, NN / 128), 256, GSMEM>>>(
            (l == 0) ? xh : xh2, whh_h, gru_bhh, gru_bih,
            x, (l == 0) ? xh2 : xh);
    }

    // 5) y = h_feature + relu(x) -> fp16
    k_buildy<<<NN * D / 256, 256>>>(h_feature);

    // 6) three residual MLPs, batched over M=12288
    h_gemm<2, true><<<dim3(D / BN, NN / BM), 256, SMEM_BYTES>>>(
        featsh, wt1_h, wt1_h + (size_t)D * D, wt1_h + 2 * (size_t)D * D,
        rb1[0], rb1[1], rb1[2], xh, NN, D, D, BSN);
    h_gemm<1, false><<<dim3(D / BN, NN / BM), 256, SMEM_BYTES>>>(
        xh, wt2_h, wt2_h + (size_t)D * D, wt2_h + 2 * (size_t)D * D,
        rb2[0], rb2[1], rb2[2], zbuf, NN, D, D, BSN);

    // 7) LayerNorm -> d_out
    k_ln<<<NN, 256>>>(rg[0], rbeta[0], rg[1], rbeta[1], rg[2], rbeta[2], out);
}